// round 2
// baseline (speedup 1.0000x reference)
#include <cuda_runtime.h>
#include <cuda_bf16.h>

// Problem constants (fixed shapes from setup_inputs)
#define CNUM 19
#define NB   32768          // histogram bins over error in [0,1]
#define HW   262144         // 512*512
#define PTOT 1048576        // 4*512*512

// Scratch (no device allocation allowed): histogram + per-class results.
// g_hist layout: [class][bin][2]  where [..][0] = non-fg count, [..][1] = fg count
__device__ __align__(16) unsigned g_hist[CNUM * NB * 2];
__device__ float    g_lossc[CNUM];
__device__ unsigned g_gts[CNUM];

// ---------------------------------------------------------------------------
// Pass 0: zero the histogram (runs every graph replay)
// ---------------------------------------------------------------------------
__global__ void zero_hist_kernel() {
    int i = blockIdx.x * blockDim.x + threadIdx.x;
    int stride = gridDim.x * blockDim.x;
    int n4 = (CNUM * NB * 2) / 4;
    uint4 z = make_uint4(0u, 0u, 0u, 0u);
    for (; i < n4; i += stride)
        reinterpret_cast<uint4*>(g_hist)[i] = z;
}

// ---------------------------------------------------------------------------
// Pass 1: softmax per pixel + per-class error histogram (19 atomics / pixel)
// NOTE: gt is int32 on the wire (JAX default config demotes int64 -> int32).
// ---------------------------------------------------------------------------
__global__ void __launch_bounds__(256) hist_kernel(
    const float* __restrict__ logits, const int* __restrict__ gt)
{
    int p = blockIdx.x * blockDim.x + threadIdx.x;
    if (p >= PTOT) return;

    int b  = p >> 18;          // batch index (HW = 2^18)
    int hw = p & (HW - 1);
    const float* base = logits + (size_t)b * CNUM * HW + hw;

    float x[CNUM];
#pragma unroll
    for (int c = 0; c < CNUM; c++) x[c] = __ldg(base + c * HW);

    int labi = gt[p];
    if (labi < 0 || labi >= CNUM) return;   // IGNORE pixels contribute nothing

    // softmax (max-subtracted)
    float m = x[0];
#pragma unroll
    for (int c = 1; c < CNUM; c++) m = fmaxf(m, x[c]);
    float s = 0.f;
#pragma unroll
    for (int c = 0; c < CNUM; c++) { float e = __expf(x[c] - m); x[c] = e; s += e; }
    float rs = __frcp_rn(s);

#pragma unroll
    for (int c = 0; c < CNUM; c++) {
        float pc = x[c] * rs;
        int   isfg = (c == labi) ? 1 : 0;
        float e = isfg ? (1.f - pc) : pc;            // |fg - p|, in [0,1]
        int bin = (int)(e * (float)NB);
        bin = bin < 0 ? 0 : (bin > NB - 1 ? NB - 1 : bin);
        atomicAdd(&g_hist[(((unsigned)c * NB + bin) << 1) + isfg], 1u);
    }
}

// ---------------------------------------------------------------------------
// Pass 2: per class — suffix counts over bins, loss_c = w*(0.5 + sum_{b>=1} J_b)
//   J_b = 1 - (gts - F_b)/(gts + U_b), F_b/U_b = suffix-inclusive counts >= bin b
// One block per class, 1024 threads, 32 bins per thread.
// ---------------------------------------------------------------------------
__global__ void __launch_bounds__(1024) loss_kernel() {
    const int c = blockIdx.x;
    const int t = threadIdx.x;
    const int CH = NB / 1024;   // 32 bins per thread (contiguous chunk)
    const uint2* h = reinterpret_cast<const uint2*>(g_hist) + (size_t)c * NB;
    const int b0 = t * CH;

    // chunk totals
    unsigned sfg = 0, snf = 0;
    for (int i = 0; i < CH; i++) {
        uint2 v = __ldg(&h[b0 + i]);
        snf += v.x; sfg += v.y;
    }

    // block-wide inclusive SUFFIX scan of chunk totals
    __shared__ unsigned sF[1024], sU[1024];
    sF[t] = sfg; sU[t] = snf;
    __syncthreads();
    for (int off = 1; off < 1024; off <<= 1) {
        unsigned f = sF[t], u = sU[t];
        unsigned fa = 0, ua = 0;
        if (t + off < 1024) { fa = sF[t + off]; ua = sU[t + off]; }
        __syncthreads();
        sF[t] = f + fa; sU[t] = u + ua;
        __syncthreads();
    }
    unsigned Finc = sF[t], Uinc = sU[t];
    unsigned gts  = sF[0];                 // total fg count for this class

    double acc = 0.0;
    if (gts > 0) {
        unsigned F = Finc - sfg;           // exclusive suffix (bins > my chunk)
        unsigned U = Uinc - snf;
        for (int i = CH - 1; i >= 0; i--) {
            int bin = b0 + i;
            uint2 v = __ldg(&h[bin]);
            F += v.y; U += v.x;            // now suffix-inclusive at 'bin'
            if (bin >= 1) {
                float J = 1.f - __fdividef((float)(gts - F), (float)(gts + U));
                acc += (double)J;
            }
        }
    }

    // block reduce
    __shared__ double sD[1024];
    sD[t] = acc;
    __syncthreads();
    for (int off = 512; off > 0; off >>= 1) {
        if (t < off) sD[t] += sD[t + off];
        __syncthreads();
    }
    if (t == 0) {
        g_lossc[c] = (float)((sD[0] + 0.5) / (double)NB);
        g_gts[c]   = gts;
    }
}

// ---------------------------------------------------------------------------
// Pass 3: average over present classes
// ---------------------------------------------------------------------------
__global__ void finalize_kernel(float* __restrict__ out) {
    if (threadIdx.x == 0 && blockIdx.x == 0) {
        float s = 0.f; int np = 0;
        for (int c = 0; c < CNUM; c++) {
            if (g_gts[c] > 0u) { s += g_lossc[c]; np++; }
        }
        out[0] = s / (float)(np > 0 ? np : 1);
    }
}

// ---------------------------------------------------------------------------
extern "C" void kernel_launch(void* const* d_in, const int* in_sizes, int n_in,
                              void* d_out, int out_size)
{
    const float* logits = (const float*)d_in[0];
    const int*   gt     = (const int*)d_in[1];
    float*       out    = (float*)d_out;

    zero_hist_kernel<<<256, 256>>>();
    hist_kernel<<<PTOT / 256, 256>>>(logits, gt);
    loss_kernel<<<CNUM, 1024>>>();
    finalize_kernel<<<1, 32>>>(out);
}